// round 14
// baseline (speedup 1.0000x reference)
#include <cuda_runtime.h>
#include <math.h>

// ============================================================================
// CKConv via FFT convolution, fused tf32 tensor-core spectrum GEMM.
//   Outf[b,o,f] = Σ_i Xf[b,i,f] · Σ_m Gf[m,f]·W3[m,o*64+i]    (Kf never stored)
// Forward: radix-8 4096 FFTs (2 real rows packed, mirror trimmed).
// Inverse: per-row N/2 trick, 2048-pt [4,8,8,8] FFT. k45: 4-iter-deep
// 5-buffer cp.async pipeline, phase-buffered deferred epilogue.
// ============================================================================

#define LL     2048
#define NFFT   4096
#define HID    128
#define NBINS  2049   // NFFT/2 + 1

__device__ float  d_h2T[HID * LL];          // [m][l]
__device__ float4 d_W3f4[64 * 8 * 8 * 32];  // [i][warp][kc2][lane] frag quads
__device__ float2 d_tw4[NFFT];
__device__ float2 d_Gf[HID * NFFT];         // [m][f] tf32, mirrored f>=2033 only
__device__ float2 d_Xf[128 * NFFT];         // [b*64+i][f], mirrored f>=2033 only
__device__ float2 d_OutfP[2][128 * NBINS];  // per-k-half partials

__device__ __forceinline__ float to_tf32(float x) {
    unsigned u;
    asm("cvt.rna.tf32.f32 %0, %1;" : "=r"(u) : "f"(x));
    return __uint_as_float(u);
}

// -------- setup: SIREN h2 (W2 smem-cached) + twiddles + W3 repack ----------
// grid 128 x 256 threads; block b handles l in [16b, 16b+16).
#define SETUP_SMEM ((16384 + 2048) * 4)    // W2 + h1 = 73728 B

__global__ void setup_h2_kernel(const float* __restrict__ W1,
                                const float* __restrict__ W2,
                                const float* __restrict__ W3) {
    extern __shared__ float sh[];
    float* W2s = sh;            // [m][j] 128x128
    float* h1s = sh + 16384;    // [li][m] 16x128
    const int t  = threadIdx.x;
    const int l0 = blockIdx.x * 16;

    const float4* W2v = (const float4*)W2;
    float4* W2sv = (float4*)W2s;
#pragma unroll
    for (int u = 0; u < 16; u++)
        W2sv[t + u * 256] = W2v[t + u * 256];
#pragma unroll
    for (int u = 0; u < 8; u++) {
        int v = t + u * 256;
        int m = v & 127, li = v >> 7;
        float rel = -1.0f + 2.0f * (float)(l0 + li) / 2047.0f;
        h1s[li * 128 + m] = sinf(30.0f * rel * W1[m]);
    }
    __syncthreads();

    const int j = t & 127, lbase = t >> 7;   // each thread: one j, 8 li's
    float acc[8];
#pragma unroll
    for (int u = 0; u < 8; u++) acc[u] = 0.0f;
#pragma unroll 8
    for (int m = 0; m < 128; m++) {
        float w = W2s[m * 128 + j];
#pragma unroll
        for (int u = 0; u < 8; u++)
            acc[u] += h1s[(lbase + 2 * u) * 128 + m] * w;
    }
#pragma unroll
    for (int u = 0; u < 8; u++)
        d_h2T[j * LL + l0 + lbase + 2 * u] = sinf(30.0f * acc[u]);

    // W3 fragment repack + twiddles: 4 elements per thread
#pragma unroll
    for (int u = 0; u < 4; u++) {
        int idx = blockIdx.x * 1024 + t * 4 + u;   // < 131072
        if (idx < NFFT) {
            double a = 2.0 * 3.14159265358979323846 * (double)idx / (double)NFFT;
            d_tw4[idx] = make_float2((float)cos(a), (float)(-sin(a)));
        }
        int lane = idx & 31;
        int kc2  = (idx >> 5) & 7;
        int w    = (idx >> 8) & 7;
        int i    = idx >> 11;
        int tg = lane & 3, g = lane >> 2;
        int col = (w * 8 + g) * 64 + i;
        int mA  = (2 * kc2) * 8 + tg;
        int mB  = (2 * kc2 + 1) * 8 + tg;
        d_W3f4[idx] = make_float4(to_tf32(W3[mA * 4096 + col]),
                                  to_tf32(W3[(mA + 4) * 4096 + col]),
                                  to_tf32(W3[mB * 4096 + col]),
                                  to_tf32(W3[(mB + 4) * 4096 + col]));
    }
}

// ------------------------------------------------------------- FFT helpers --
__device__ __forceinline__ int rev8(int d) {
    return ((d & 7) << 9) | (((d >> 3) & 7) << 6) |
           (((d >> 6) & 7) << 3) | ((d >> 9) & 7);
}
__device__ __forceinline__ float2 cmul(float2 a, float2 b) {
    return make_float2(a.x * b.x - a.y * b.y, a.x * b.y + a.y * b.x);
}
#define SQRT1_2 0.70710678118654752f

__device__ __forceinline__ void bfly8(float2* u) {
    float2 ea = make_float2(u[0].x + u[4].x, u[0].y + u[4].y);
    float2 eb = make_float2(u[0].x - u[4].x, u[0].y - u[4].y);
    float2 ec = make_float2(u[2].x + u[6].x, u[2].y + u[6].y);
    float2 ed = make_float2(u[2].x - u[6].x, u[2].y - u[6].y);
    float2 E0 = make_float2(ea.x + ec.x, ea.y + ec.y);
    float2 E1 = make_float2(eb.x + ed.y, eb.y - ed.x);
    float2 E2 = make_float2(ea.x - ec.x, ea.y - ec.y);
    float2 E3 = make_float2(eb.x - ed.y, eb.y + ed.x);
    float2 oa = make_float2(u[1].x + u[5].x, u[1].y + u[5].y);
    float2 ob = make_float2(u[1].x - u[5].x, u[1].y - u[5].y);
    float2 oc = make_float2(u[3].x + u[7].x, u[3].y + u[7].y);
    float2 od = make_float2(u[3].x - u[7].x, u[3].y - u[7].y);
    float2 O0 = make_float2(oa.x + oc.x, oa.y + oc.y);
    float2 O1 = make_float2(ob.x + od.y, ob.y - od.x);
    float2 O2 = make_float2(oa.x - oc.x, oa.y - oc.y);
    float2 O3 = make_float2(ob.x - od.y, ob.y + od.x);
    float2 T1 = make_float2(SQRT1_2 * (O1.x + O1.y), SQRT1_2 * (O1.y - O1.x));
    float2 T2 = make_float2(O2.y, -O2.x);
    float2 T3 = make_float2(SQRT1_2 * (O3.y - O3.x), -SQRT1_2 * (O3.x + O3.y));
    u[0] = make_float2(E0.x + O0.x, E0.y + O0.y);
    u[4] = make_float2(E0.x - O0.x, E0.y - O0.y);
    u[1] = make_float2(E1.x + T1.x, E1.y + T1.y);
    u[5] = make_float2(E1.x - T1.x, E1.y - T1.y);
    u[2] = make_float2(E2.x + T2.x, E2.y + T2.y);
    u[6] = make_float2(E2.x - T2.x, E2.y - T2.y);
    u[3] = make_float2(E3.x + T3.x, E3.y + T3.y);
    u[7] = make_float2(E3.x - T3.x, E3.y - T3.y);
}

// ------------------- 4096-pt radix-8 core (512 threads, 4 stages) ----------
__device__ __forceinline__ void fft8_core(float2* buf) {
    const int tid = threadIdx.x;
    __syncthreads();
    {
        float4* b4 = (float4*)(buf + tid * 8);
        float2 u[8];
#pragma unroll
        for (int h = 0; h < 4; h++) {
            float4 v = b4[h];
            u[2 * h]     = make_float2(v.x, v.y);
            u[2 * h + 1] = make_float2(v.z, v.w);
        }
        bfly8(u);
#pragma unroll
        for (int h = 0; h < 4; h++)
            b4[h] = make_float4(u[2 * h].x, u[2 * h].y,
                                u[2 * h + 1].x, u[2 * h + 1].y);
    }
#pragma unroll
    for (int st = 1; st < 4; st++) {
        const int q = 1 << (3 * st);
        const int tstep = NFFT >> (3 * st + 3);
        __syncthreads();
        const int j = tid & (q - 1);
        const int base = ((tid >> (3 * st)) << (3 * st + 3)) + j;
        float2 u[8];
        u[0] = buf[base];
#pragma unroll
        for (int t = 1; t < 8; t++)
            u[t] = cmul(buf[base + t * q], d_tw4[j * t * tstep]);
        bfly8(u);
#pragma unroll
        for (int t = 0; t < 8; t++)
            buf[base + t * q] = u[t];
    }
    __syncthreads();
}

// --------------- 2048-pt mixed-radix [4,8,8,8] core (256 threads) ----------
__device__ __forceinline__ int addr2048(int s) {
    return (s >> 9) + 4 * ((s >> 6) & 7) + 32 * ((s >> 3) & 7) + 256 * (s & 7);
}
__device__ __forceinline__ void fft2048_core(float2* buf) {
    const int tid = threadIdx.x;
    __syncthreads();
#pragma unroll
    for (int k = 0; k < 2; k++) {
        float4* b4 = (float4*)(buf + ((tid + (k << 8)) << 2));
        float4 lo = b4[0], hi = b4[1];
        float2 u0 = make_float2(lo.x, lo.y), u1 = make_float2(lo.z, lo.w);
        float2 u2 = make_float2(hi.x, hi.y), u3 = make_float2(hi.z, hi.w);
        float2 a = make_float2(u0.x + u2.x, u0.y + u2.y);
        float2 b = make_float2(u0.x - u2.x, u0.y - u2.y);
        float2 c = make_float2(u1.x + u3.x, u1.y + u3.y);
        float2 d = make_float2(u1.x - u3.x, u1.y - u3.y);
        b4[0] = make_float4(a.x + c.x, a.y + c.y, b.x + d.y, b.y - d.x);
        b4[1] = make_float4(a.x - c.x, a.y - c.y, b.x - d.y, b.y + d.x);
    }
#pragma unroll
    for (int st = 0; st < 3; st++) {
        const int q = 4 << (3 * st);
        const int tstep = 128 >> (3 * st);
        const int sh = 2 + 3 * st;
        __syncthreads();
        const int j = tid & (q - 1);
        const int base = ((tid >> sh) << (sh + 3)) + j;
        float2 u[8];
        u[0] = buf[base];
#pragma unroll
        for (int t = 1; t < 8; t++)
            u[t] = cmul(buf[base + t * q], d_tw4[j * t * tstep]);
        bfly8(u);
#pragma unroll
        for (int t = 0; t < 8; t++)
            buf[base + t * q] = u[t];
    }
    __syncthreads();
}

// ---------------------------- forward FFTs, two real rows packed per block --
__global__ void fft_gx_kernel(const float* __restrict__ x) {
    __shared__ float2 buf[NFFT];
    int blk = blockIdx.x;
    bool isg = blk < 64;
    int r0 = isg ? 2 * blk : 2 * (blk - 64);
    for (int s = threadIdx.x; s < NFFT; s += 512) {
        float va = 0.0f, vb = 0.0f;
        if (s < LL) {
            if (isg) {
                va = d_h2T[r0 * LL + (LL - 1 - s)];
                vb = d_h2T[(r0 + 1) * LL + (LL - 1 - s)];
            } else {
                va = x[r0 * LL + s];
                vb = x[(r0 + 1) * LL + s];
            }
        }
        buf[rev8(s)] = make_float2(va, vb);
    }
    fft8_core(buf);
    // mirror only f in [2033,2048): k45 reads at most f = 2063.
    for (int f = threadIdx.x; f <= 2048; f += 512) {
        float2 Zf = buf[f];
        float2 Zc = buf[(NFFT - f) & (NFFT - 1)];
        float2 A = make_float2((Zf.x + Zc.x) * 0.5f, (Zf.y - Zc.y) * 0.5f);
        float2 B = make_float2((Zf.y + Zc.y) * 0.5f, (Zc.x - Zf.x) * 0.5f);
        if (isg) {
            A = make_float2(to_tf32(A.x), to_tf32(A.y));
            B = make_float2(to_tf32(B.x), to_tf32(B.y));
            d_Gf[r0 * NFFT + f]       = A;
            d_Gf[(r0 + 1) * NFFT + f] = B;
            if (f >= 2033 && f < 2048) {
                d_Gf[r0 * NFFT + NFFT - f]       = make_float2(A.x, -A.y);
                d_Gf[(r0 + 1) * NFFT + NFFT - f] = make_float2(B.x, -B.y);
            }
        } else {
            d_Xf[r0 * NFFT + f]       = A;
            d_Xf[(r0 + 1) * NFFT + f] = B;
            if (f >= 2033 && f < 2048) {
                d_Xf[r0 * NFFT + NFFT - f]       = make_float2(A.x, -A.y);
                d_Xf[(r0 + 1) * NFFT + NFFT - f] = make_float2(B.x, -B.y);
            }
        }
    }
}

// ----------------------- k45: fused kernel-spectrum GEMM + per-bin mixing --
#define MMA_TF32(C, A, B0, B1)                                              \
    asm volatile("mma.sync.aligned.m16n8k8.row.col.f32.tf32.tf32.f32 "      \
        "{%0,%1,%2,%3}, {%4,%5,%6,%7}, {%8,%9}, {%0,%1,%2,%3};"             \
        : "+f"(C[0]), "+f"(C[1]), "+f"(C[2]), "+f"(C[3])                    \
        : "r"(A[0]), "r"(A[1]), "r"(A[2]), "r"(A[3]), "r"(B0), "r"(B1))

#define CP16(dst_u32, src_ptr)                                              \
    asm volatile("cp.async.cg.shared.global [%0], [%1], 16;"                \
                 :: "r"(dst_u32), "l"(src_ptr))

#define XS_FLOATS   (128 * 16 * 2)
#define SLICE_F4    128
#define NBUF        5
#define K45_SMEM    (XS_FLOATS * 4 + 8 * NBUF * SLICE_F4 * 16)   // 96 KB

__global__ void __launch_bounds__(256, 2) k45_kernel() {
    extern __shared__ float smem[];
    float2* Xs = (float2*)smem;                 // [i][ff][b] layout

    const int f0   = blockIdx.x * 16;
    const int kh   = blockIdx.y;
    const int kofs = kh * 64;
    const int tid  = threadIdx.x;
    const int lane = tid & 31;
    const int warp = tid >> 5;
    const int g    = lane >> 2;
    const int tg   = lane & 3;
    const int obase = warp * 8;

    float4* Bw = (float4*)(smem + XS_FLOATS) + warp * (NBUF * SLICE_F4);
    unsigned bw_base = (unsigned)__cvta_generic_to_shared(Bw);

#define LOAD_SLICE(i_, buf_)                                                \
    {                                                                       \
        const float4* srcb = d_W3f4 + (((i_) * 8 + warp) * 8 + kh * 4) * 32;\
        unsigned dstb = bw_base + (buf_) * (SLICE_F4 * 16);                 \
        _Pragma("unroll")                                                   \
        for (int j = 0; j < 4; j++)                                         \
            CP16(dstb + (lane + (j << 5)) * 16, srcb + lane + (j << 5));    \
    }

    LOAD_SLICE(0, 0); asm volatile("cp.async.commit_group;");
    LOAD_SLICE(1, 1); asm volatile("cp.async.commit_group;");
    LOAD_SLICE(2, 2); asm volatile("cp.async.commit_group;");
    LOAD_SLICE(3, 3); asm volatile("cp.async.commit_group;");

    // Xs fill, [i][ff][b]: both batches adjacent -> epilogue LDS.128
    for (int idx = tid; idx < 128 * 16; idx += 256) {
        int row = idx >> 4, ff = idx & 15;
        int b = row >> 6, i = row & 63;
        Xs[(i * 16 + ff) * 2 + b] = d_Xf[row * NFFT + f0 + ff];
    }

    unsigned aR[8][4], aI[8][4];
#pragma unroll
    for (int k0 = 0; k0 < 8; k0++) {
        int kk = kofs + k0 * 8;
        float2 v0 = d_Gf[(kk + tg)     * NFFT + f0 + g];
        float2 v1 = d_Gf[(kk + tg)     * NFFT + f0 + g + 8];
        float2 v2 = d_Gf[(kk + tg + 4) * NFFT + f0 + g];
        float2 v3 = d_Gf[(kk + tg + 4) * NFFT + f0 + g + 8];
        aR[k0][0] = __float_as_uint(v0.x); aI[k0][0] = __float_as_uint(v0.y);
        aR[k0][1] = __float_as_uint(v1.x); aI[k0][1] = __float_as_uint(v1.y);
        aR[k0][2] = __float_as_uint(v2.x); aI[k0][2] = __float_as_uint(v2.y);
        aR[k0][3] = __float_as_uint(v3.x); aI[k0][3] = __float_as_uint(v3.y);
    }

    float oR[2][2][2] = {}, oI[2][2][2] = {};
    float cR[2][4], cI[2][4];
    int use_buf = 0, pre_buf = 4;

    __syncthreads();

#pragma unroll 2
    for (int i = 0; i < 64; i++) {
        const int p = i & 1;
        if (i + 4 < 64) LOAD_SLICE(i + 4, pre_buf);
        asm volatile("cp.async.commit_group;");      // real or empty group
        asm volatile("cp.async.wait_group 4;");      // slice i is ready
        __syncwarp();

        const float4* Bp = Bw + use_buf * SLICE_F4 + lane;
#pragma unroll
        for (int j = 0; j < 4; j++) { cR[p][j] = 0.f; cI[p][j] = 0.f; }
#pragma unroll
        for (int q = 0; q < 4; q++) {
            float4 bv = Bp[q * 32];
            unsigned b0 = __float_as_uint(bv.x), b1 = __float_as_uint(bv.y);
            unsigned b2 = __float_as_uint(bv.z), b3 = __float_as_uint(bv.w);
            MMA_TF32(cR[p], aR[2 * q],     b0, b1);
            MMA_TF32(cI[p], aI[2 * q],     b0, b1);
            MMA_TF32(cR[p], aR[2 * q + 1], b2, b3);
            MMA_TF32(cI[p], aI[2 * q + 1], b2, b3);
        }

        if (i > 0) {
            const int ip = i - 1, pp = p ^ 1;
#pragma unroll
            for (int rr = 0; rr < 2; rr++) {
                int flocal = g + rr * 8;
                float4 xv4 = ((const float4*)Xs)[ip * 16 + flocal];
                float2 xv[2] = { make_float2(xv4.x, xv4.y),
                                 make_float2(xv4.z, xv4.w) };
#pragma unroll
                for (int b = 0; b < 2; b++)
#pragma unroll
                    for (int cc = 0; cc < 2; cc++) {
                        float kr = cR[pp][rr * 2 + cc];
                        float ki = cI[pp][rr * 2 + cc];
                        oR[b][rr][cc] += xv[b].x * kr - xv[b].y * ki;
                        oI[b][rr][cc] += xv[b].x * ki + xv[b].y * kr;
                    }
            }
        }
        if (++use_buf == NBUF) use_buf = 0;
        if (++pre_buf == NBUF) pre_buf = 0;
    }
    {   // final epilogue: iteration 63 lives in phase 1
        const int ip = 63, pp = 1;
#pragma unroll
        for (int rr = 0; rr < 2; rr++) {
            int flocal = g + rr * 8;
            float4 xv4 = ((const float4*)Xs)[ip * 16 + flocal];
            float2 xv[2] = { make_float2(xv4.x, xv4.y),
                             make_float2(xv4.z, xv4.w) };
#pragma unroll
            for (int b = 0; b < 2; b++)
#pragma unroll
                for (int cc = 0; cc < 2; cc++) {
                    float kr = cR[pp][rr * 2 + cc];
                    float ki = cI[pp][rr * 2 + cc];
                    oR[b][rr][cc] += xv[b].x * kr - xv[b].y * ki;
                    oI[b][rr][cc] += xv[b].x * ki + xv[b].y * kr;
                }
        }
    }

#pragma unroll
    for (int rr = 0; rr < 2; rr++) {
        int f = f0 + g + rr * 8;
        if (f < NBINS) {
#pragma unroll
            for (int b = 0; b < 2; b++)
#pragma unroll
                for (int cc = 0; cc < 2; cc++) {
                    int o = obase + tg * 2 + cc;
                    d_OutfP[kh][(b * 64 + o) * NBINS + f] =
                        make_float2(oR[b][rr][cc], oI[b][rr][cc]);
                }
        }
    }
}

// ---------------- inverse FFT: ONE row per block, N/2 real-IFFT trick ------
__global__ void fft_inv_kernel(float* __restrict__ out) {
    __shared__ float2 buf[2048];
    int r = blockIdx.x;   // 0..127
    const float2* P0 = d_OutfP[0] + (size_t)r * NBINS;
    const float2* P1 = d_OutfP[1] + (size_t)r * NBINS;
    for (int s = threadIdx.x; s < 2048; s += 256) {
        int ms = 2048 - s;
        float2 Yf = make_float2(P0[s].x + P1[s].x,  P0[s].y + P1[s].y);
        float2 Ym = make_float2(P0[ms].x + P1[ms].x, P0[ms].y + P1[ms].y);
        float2 A = make_float2(0.5f * (Yf.x + Ym.x), 0.5f * (Yf.y - Ym.y));
        float2 D = make_float2(0.5f * (Yf.x - Ym.x), 0.5f * (Yf.y + Ym.y));
        float2 tw = d_tw4[s];
        float2 B = make_float2(D.x * tw.x + D.y * tw.y,
                               D.y * tw.x - D.x * tw.y);
        float2 Z = make_float2(A.x - B.y, A.y + B.x);
        buf[addr2048(s)] = make_float2(Z.x, -Z.y);
    }
    fft2048_core(buf);
    const float inv = 1.0f / 2048.0f;
    float2* out2 = (float2*)out;
    for (int k = threadIdx.x; k < 1024; k += 256) {
        float2 F = buf[k];
        out2[r * 1024 + k] = make_float2(F.x * inv, -F.y * inv);
    }
}

// ============================================================================
extern "C" void kernel_launch(void* const* d_in, const int* in_sizes, int n_in,
                              void* d_out, int out_size) {
    (void)in_sizes; (void)n_in; (void)out_size;
    const float* x  = (const float*)d_in[0];
    const float* W1 = (const float*)d_in[1];
    const float* W2 = (const float*)d_in[2];
    const float* W3 = (const float*)d_in[3];
    float* out = (float*)d_out;

    cudaFuncSetAttribute(k45_kernel,
                         cudaFuncAttributeMaxDynamicSharedMemorySize, K45_SMEM);
    cudaFuncSetAttribute(setup_h2_kernel,
                         cudaFuncAttributeMaxDynamicSharedMemorySize, SETUP_SMEM);

    setup_h2_kernel<<<128, 256, SETUP_SMEM>>>(W1, W2, W3);
    fft_gx_kernel<<<128, 512>>>(x);
    k45_kernel<<<dim3(129, 2), 256, K45_SMEM>>>();
    fft_inv_kernel<<<128, 256>>>(out);
}

// round 15
// speedup vs baseline: 1.0004x; 1.0004x over previous
#include <cuda_runtime.h>
#include <math.h>

// ============================================================================
// CKConv via FFT convolution, fused tf32 tensor-core spectrum GEMM.
//   Outf[b,o,f] = Σ_i Xf[b,i,f] · Σ_m Gf[m,f]·W3[m,o*64+i]    (Kf never stored)
// setup: W2 smem-cached SIREN + W3 frag repack. Forward: radix-8 4096 FFTs
// (2 real rows packed, mirrors trimmed to f>=2033). k45: R12 version (4-buf
// depth-3 cp.async, phase-buffered deferred epilogue). Inverse: N/2 trick.
// ============================================================================

#define LL     2048
#define NFFT   4096
#define HID    128
#define NBINS  2049   // NFFT/2 + 1

__device__ float  d_h2T[HID * LL];          // [m][l]
__device__ float4 d_W3f4[64 * 8 * 8 * 32];  // [i][warp][kc2][lane] frag quads
__device__ float2 d_tw4[NFFT];
__device__ float2 d_Gf[HID * NFFT];         // [m][f] tf32, mirrored f>=2033 only
__device__ float2 d_Xf[128 * NFFT];         // [b*64+i][f], mirrored f>=2033 only
__device__ float2 d_OutfP[2][128 * NBINS];  // per-k-half partials

__device__ __forceinline__ float to_tf32(float x) {
    unsigned u;
    asm("cvt.rna.tf32.f32 %0, %1;" : "=r"(u) : "f"(x));
    return __uint_as_float(u);
}

// -------- setup: SIREN h2 (W2 smem-cached) + twiddles + W3 repack ----------
#define SETUP_SMEM ((16384 + 2048) * 4)    // W2 + h1 = 73728 B

__global__ void setup_h2_kernel(const float* __restrict__ W1,
                                const float* __restrict__ W2,
                                const float* __restrict__ W3) {
    extern __shared__ float sh[];
    float* W2s = sh;            // [m][j] 128x128
    float* h1s = sh + 16384;    // [li][m] 16x128
    const int t  = threadIdx.x;
    const int l0 = blockIdx.x * 16;

    const float4* W2v = (const float4*)W2;
    float4* W2sv = (float4*)W2s;
#pragma unroll
    for (int u = 0; u < 16; u++)
        W2sv[t + u * 256] = W2v[t + u * 256];
#pragma unroll
    for (int u = 0; u < 8; u++) {
        int v = t + u * 256;
        int m = v & 127, li = v >> 7;
        float rel = -1.0f + 2.0f * (float)(l0 + li) / 2047.0f;
        h1s[li * 128 + m] = sinf(30.0f * rel * W1[m]);
    }
    __syncthreads();

    const int j = t & 127, lbase = t >> 7;
    float acc[8];
#pragma unroll
    for (int u = 0; u < 8; u++) acc[u] = 0.0f;
#pragma unroll 8
    for (int m = 0; m < 128; m++) {
        float w = W2s[m * 128 + j];
#pragma unroll
        for (int u = 0; u < 8; u++)
            acc[u] += h1s[(lbase + 2 * u) * 128 + m] * w;
    }
#pragma unroll
    for (int u = 0; u < 8; u++)
        d_h2T[j * LL + l0 + lbase + 2 * u] = sinf(30.0f * acc[u]);

#pragma unroll
    for (int u = 0; u < 4; u++) {
        int idx = blockIdx.x * 1024 + t * 4 + u;   // < 131072
        if (idx < NFFT) {
            double a = 2.0 * 3.14159265358979323846 * (double)idx / (double)NFFT;
            d_tw4[idx] = make_float2((float)cos(a), (float)(-sin(a)));
        }
        int lane = idx & 31;
        int kc2  = (idx >> 5) & 7;
        int w    = (idx >> 8) & 7;
        int i    = idx >> 11;
        int tg = lane & 3, g = lane >> 2;
        int col = (w * 8 + g) * 64 + i;
        int mA  = (2 * kc2) * 8 + tg;
        int mB  = (2 * kc2 + 1) * 8 + tg;
        d_W3f4[idx] = make_float4(to_tf32(W3[mA * 4096 + col]),
                                  to_tf32(W3[(mA + 4) * 4096 + col]),
                                  to_tf32(W3[mB * 4096 + col]),
                                  to_tf32(W3[(mB + 4) * 4096 + col]));
    }
}

// ------------------------------------------------------------- FFT helpers --
__device__ __forceinline__ int rev8(int d) {
    return ((d & 7) << 9) | (((d >> 3) & 7) << 6) |
           (((d >> 6) & 7) << 3) | ((d >> 9) & 7);
}
__device__ __forceinline__ float2 cmul(float2 a, float2 b) {
    return make_float2(a.x * b.x - a.y * b.y, a.x * b.y + a.y * b.x);
}
#define SQRT1_2 0.70710678118654752f

__device__ __forceinline__ void bfly8(float2* u) {
    float2 ea = make_float2(u[0].x + u[4].x, u[0].y + u[4].y);
    float2 eb = make_float2(u[0].x - u[4].x, u[0].y - u[4].y);
    float2 ec = make_float2(u[2].x + u[6].x, u[2].y + u[6].y);
    float2 ed = make_float2(u[2].x - u[6].x, u[2].y - u[6].y);
    float2 E0 = make_float2(ea.x + ec.x, ea.y + ec.y);
    float2 E1 = make_float2(eb.x + ed.y, eb.y - ed.x);
    float2 E2 = make_float2(ea.x - ec.x, ea.y - ec.y);
    float2 E3 = make_float2(eb.x - ed.y, eb.y + ed.x);
    float2 oa = make_float2(u[1].x + u[5].x, u[1].y + u[5].y);
    float2 ob = make_float2(u[1].x - u[5].x, u[1].y - u[5].y);
    float2 oc = make_float2(u[3].x + u[7].x, u[3].y + u[7].y);
    float2 od = make_float2(u[3].x - u[7].x, u[3].y - u[7].y);
    float2 O0 = make_float2(oa.x + oc.x, oa.y + oc.y);
    float2 O1 = make_float2(ob.x + od.y, ob.y - od.x);
    float2 O2 = make_float2(oa.x - oc.x, oa.y - oc.y);
    float2 O3 = make_float2(ob.x - od.y, ob.y + od.x);
    float2 T1 = make_float2(SQRT1_2 * (O1.x + O1.y), SQRT1_2 * (O1.y - O1.x));
    float2 T2 = make_float2(O2.y, -O2.x);
    float2 T3 = make_float2(SQRT1_2 * (O3.y - O3.x), -SQRT1_2 * (O3.x + O3.y));
    u[0] = make_float2(E0.x + O0.x, E0.y + O0.y);
    u[4] = make_float2(E0.x - O0.x, E0.y - O0.y);
    u[1] = make_float2(E1.x + T1.x, E1.y + T1.y);
    u[5] = make_float2(E1.x - T1.x, E1.y - T1.y);
    u[2] = make_float2(E2.x + T2.x, E2.y + T2.y);
    u[6] = make_float2(E2.x - T2.x, E2.y - T2.y);
    u[3] = make_float2(E3.x + T3.x, E3.y + T3.y);
    u[7] = make_float2(E3.x - T3.x, E3.y - T3.y);
}

// ------------------- 4096-pt radix-8 core (512 threads, 4 stages) ----------
__device__ __forceinline__ void fft8_core(float2* buf) {
    const int tid = threadIdx.x;
    __syncthreads();
    {
        float4* b4 = (float4*)(buf + tid * 8);
        float2 u[8];
#pragma unroll
        for (int h = 0; h < 4; h++) {
            float4 v = b4[h];
            u[2 * h]     = make_float2(v.x, v.y);
            u[2 * h + 1] = make_float2(v.z, v.w);
        }
        bfly8(u);
#pragma unroll
        for (int h = 0; h < 4; h++)
            b4[h] = make_float4(u[2 * h].x, u[2 * h].y,
                                u[2 * h + 1].x, u[2 * h + 1].y);
    }
#pragma unroll
    for (int st = 1; st < 4; st++) {
        const int q = 1 << (3 * st);
        const int tstep = NFFT >> (3 * st + 3);
        __syncthreads();
        const int j = tid & (q - 1);
        const int base = ((tid >> (3 * st)) << (3 * st + 3)) + j;
        float2 u[8];
        u[0] = buf[base];
#pragma unroll
        for (int t = 1; t < 8; t++)
            u[t] = cmul(buf[base + t * q], d_tw4[j * t * tstep]);
        bfly8(u);
#pragma unroll
        for (int t = 0; t < 8; t++)
            buf[base + t * q] = u[t];
    }
    __syncthreads();
}

// --------------- 2048-pt mixed-radix [4,8,8,8] core (256 threads) ----------
__device__ __forceinline__ int addr2048(int s) {
    return (s >> 9) + 4 * ((s >> 6) & 7) + 32 * ((s >> 3) & 7) + 256 * (s & 7);
}
__device__ __forceinline__ void fft2048_core(float2* buf) {
    const int tid = threadIdx.x;
    __syncthreads();
#pragma unroll
    for (int k = 0; k < 2; k++) {
        float4* b4 = (float4*)(buf + ((tid + (k << 8)) << 2));
        float4 lo = b4[0], hi = b4[1];
        float2 u0 = make_float2(lo.x, lo.y), u1 = make_float2(lo.z, lo.w);
        float2 u2 = make_float2(hi.x, hi.y), u3 = make_float2(hi.z, hi.w);
        float2 a = make_float2(u0.x + u2.x, u0.y + u2.y);
        float2 b = make_float2(u0.x - u2.x, u0.y - u2.y);
        float2 c = make_float2(u1.x + u3.x, u1.y + u3.y);
        float2 d = make_float2(u1.x - u3.x, u1.y - u3.y);
        b4[0] = make_float4(a.x + c.x, a.y + c.y, b.x + d.y, b.y - d.x);
        b4[1] = make_float4(a.x - c.x, a.y - c.y, b.x - d.y, b.y + d.x);
    }
#pragma unroll
    for (int st = 0; st < 3; st++) {
        const int q = 4 << (3 * st);
        const int tstep = 128 >> (3 * st);
        const int sh = 2 + 3 * st;
        __syncthreads();
        const int j = tid & (q - 1);
        const int base = ((tid >> sh) << (sh + 3)) + j;
        float2 u[8];
        u[0] = buf[base];
#pragma unroll
        for (int t = 1; t < 8; t++)
            u[t] = cmul(buf[base + t * q], d_tw4[j * t * tstep]);
        bfly8(u);
#pragma unroll
        for (int t = 0; t < 8; t++)
            buf[base + t * q] = u[t];
    }
    __syncthreads();
}

// ---------------------------- forward FFTs, two real rows packed per block --
__global__ void fft_gx_kernel(const float* __restrict__ x) {
    __shared__ float2 buf[NFFT];
    int blk = blockIdx.x;
    bool isg = blk < 64;
    int r0 = isg ? 2 * blk : 2 * (blk - 64);
    for (int s = threadIdx.x; s < NFFT; s += 512) {
        float va = 0.0f, vb = 0.0f;
        if (s < LL) {
            if (isg) {
                va = d_h2T[r0 * LL + (LL - 1 - s)];
                vb = d_h2T[(r0 + 1) * LL + (LL - 1 - s)];
            } else {
                va = x[r0 * LL + s];
                vb = x[(r0 + 1) * LL + s];
            }
        }
        buf[rev8(s)] = make_float2(va, vb);
    }
    fft8_core(buf);
    // mirror only f in [2033,2048): k45 reads at most f = 2063.
    for (int f = threadIdx.x; f <= 2048; f += 512) {
        float2 Zf = buf[f];
        float2 Zc = buf[(NFFT - f) & (NFFT - 1)];
        float2 A = make_float2((Zf.x + Zc.x) * 0.5f, (Zf.y - Zc.y) * 0.5f);
        float2 B = make_float2((Zf.y + Zc.y) * 0.5f, (Zc.x - Zf.x) * 0.5f);
        if (isg) {
            A = make_float2(to_tf32(A.x), to_tf32(A.y));
            B = make_float2(to_tf32(B.x), to_tf32(B.y));
            d_Gf[r0 * NFFT + f]       = A;
            d_Gf[(r0 + 1) * NFFT + f] = B;
            if (f >= 2033 && f < 2048) {
                d_Gf[r0 * NFFT + NFFT - f]       = make_float2(A.x, -A.y);
                d_Gf[(r0 + 1) * NFFT + NFFT - f] = make_float2(B.x, -B.y);
            }
        } else {
            d_Xf[r0 * NFFT + f]       = A;
            d_Xf[(r0 + 1) * NFFT + f] = B;
            if (f >= 2033 && f < 2048) {
                d_Xf[r0 * NFFT + NFFT - f]       = make_float2(A.x, -A.y);
                d_Xf[(r0 + 1) * NFFT + NFFT - f] = make_float2(B.x, -B.y);
            }
        }
    }
}

// ----------------------- k45: fused kernel-spectrum GEMM + per-bin mixing --
// (exact R12 version: 4 buffers, depth-3, constant-folded (i&3) indices)
#define MMA_TF32(C, A, B0, B1)                                              \
    asm volatile("mma.sync.aligned.m16n8k8.row.col.f32.tf32.tf32.f32 "      \
        "{%0,%1,%2,%3}, {%4,%5,%6,%7}, {%8,%9}, {%0,%1,%2,%3};"             \
        : "+f"(C[0]), "+f"(C[1]), "+f"(C[2]), "+f"(C[3])                    \
        : "r"(A[0]), "r"(A[1]), "r"(A[2]), "r"(A[3]), "r"(B0), "r"(B1))

#define CP16(dst_u32, src_ptr)                                              \
    asm volatile("cp.async.cg.shared.global [%0], [%1], 16;"                \
                 :: "r"(dst_u32), "l"(src_ptr))

#define XS_FLOATS   (128 * 16 * 2)
#define SLICE_F4    128
#define K45_SMEM    (XS_FLOATS * 4 + 8 * 4 * SLICE_F4 * 16)

__global__ void __launch_bounds__(256, 2) k45_kernel() {
    extern __shared__ float smem[];
    float2* Xs = (float2*)smem;

    const int f0   = blockIdx.x * 16;
    const int kh   = blockIdx.y;
    const int kofs = kh * 64;
    const int tid  = threadIdx.x;
    const int lane = tid & 31;
    const int warp = tid >> 5;
    const int g    = lane >> 2;
    const int tg   = lane & 3;
    const int obase = warp * 8;

    float4* Bw = (float4*)(smem + XS_FLOATS) + warp * (4 * SLICE_F4);
    unsigned bw_base = (unsigned)__cvta_generic_to_shared(Bw);

#define LOAD_SLICE(i_, buf_)                                                \
    {                                                                       \
        const float4* srcb = d_W3f4 + (((i_) * 8 + warp) * 8 + kh * 4) * 32;\
        unsigned dstb = bw_base + (buf_) * (SLICE_F4 * 16);                 \
        _Pragma("unroll")                                                   \
        for (int j = 0; j < 4; j++)                                         \
            CP16(dstb + (lane + (j << 5)) * 16, srcb + lane + (j << 5));    \
    }

    LOAD_SLICE(0, 0); asm volatile("cp.async.commit_group;");
    LOAD_SLICE(1, 1); asm volatile("cp.async.commit_group;");
    LOAD_SLICE(2, 2); asm volatile("cp.async.commit_group;");

    for (int idx = tid; idx < 128 * 16; idx += 256) {
        int row = idx >> 4, ff = idx & 15;
        Xs[idx] = d_Xf[row * NFFT + f0 + ff];
    }

    unsigned aR[8][4], aI[8][4];
#pragma unroll
    for (int k0 = 0; k0 < 8; k0++) {
        int kk = kofs + k0 * 8;
        float2 v0 = d_Gf[(kk + tg)     * NFFT + f0 + g];
        float2 v1 = d_Gf[(kk + tg)     * NFFT + f0 + g + 8];
        float2 v2 = d_Gf[(kk + tg + 4) * NFFT + f0 + g];
        float2 v3 = d_Gf[(kk + tg + 4) * NFFT + f0 + g + 8];
        aR[k0][0] = __float_as_uint(v0.x); aI[k0][0] = __float_as_uint(v0.y);
        aR[k0][1] = __float_as_uint(v1.x); aI[k0][1] = __float_as_uint(v1.y);
        aR[k0][2] = __float_as_uint(v2.x); aI[k0][2] = __float_as_uint(v2.y);
        aR[k0][3] = __float_as_uint(v3.x); aI[k0][3] = __float_as_uint(v3.y);
    }

    float oR[2][2][2] = {}, oI[2][2][2] = {};
    float cR[2][4], cI[2][4];

    __syncthreads();

#pragma unroll 2
    for (int i = 0; i < 64; i++) {
        const int p = i & 1;
        if (i + 3 < 64) LOAD_SLICE(i + 3, (i + 3) & 3);
        asm volatile("cp.async.commit_group;");
        asm volatile("cp.async.wait_group 3;");
        __syncwarp();

        const float4* Bp = Bw + (i & 3) * SLICE_F4 + lane;
#pragma unroll
        for (int j = 0; j < 4; j++) { cR[p][j] = 0.f; cI[p][j] = 0.f; }
#pragma unroll
        for (int q = 0; q < 4; q++) {
            float4 bv = Bp[q * 32];
            unsigned b0 = __float_as_uint(bv.x), b1 = __float_as_uint(bv.y);
            unsigned b2 = __float_as_uint(bv.z), b3 = __float_as_uint(bv.w);
            MMA_TF32(cR[p], aR[2 * q],     b0, b1);
            MMA_TF32(cI[p], aI[2 * q],     b0, b1);
            MMA_TF32(cR[p], aR[2 * q + 1], b2, b3);
            MMA_TF32(cI[p], aI[2 * q + 1], b2, b3);
        }

        if (i > 0) {
            const int ip = i - 1, pp = p ^ 1;
#pragma unroll
            for (int rr = 0; rr < 2; rr++) {
                int flocal = g + rr * 8;
#pragma unroll
                for (int b = 0; b < 2; b++) {
                    float2 xv = Xs[(b * 64 + ip) * 16 + flocal];
#pragma unroll
                    for (int cc = 0; cc < 2; cc++) {
                        float kr = cR[pp][rr * 2 + cc];
                        float ki = cI[pp][rr * 2 + cc];
                        oR[b][rr][cc] += xv.x * kr - xv.y * ki;
                        oI[b][rr][cc] += xv.x * ki + xv.y * kr;
                    }
                }
            }
        }
    }
    {
        const int ip = 63, pp = 1;
#pragma unroll
        for (int rr = 0; rr < 2; rr++) {
            int flocal = g + rr * 8;
#pragma unroll
            for (int b = 0; b < 2; b++) {
                float2 xv = Xs[(b * 64 + ip) * 16 + flocal];
#pragma unroll
                for (int cc = 0; cc < 2; cc++) {
                    float kr = cR[pp][rr * 2 + cc];
                    float ki = cI[pp][rr * 2 + cc];
                    oR[b][rr][cc] += xv.x * kr - xv.y * ki;
                    oI[b][rr][cc] += xv.x * ki + xv.y * kr;
                }
            }
        }
    }

#pragma unroll
    for (int rr = 0; rr < 2; rr++) {
        int f = f0 + g + rr * 8;
        if (f < NBINS) {
#pragma unroll
            for (int b = 0; b < 2; b++)
#pragma unroll
                for (int cc = 0; cc < 2; cc++) {
                    int o = obase + tg * 2 + cc;
                    d_OutfP[kh][(b * 64 + o) * NBINS + f] =
                        make_float2(oR[b][rr][cc], oI[b][rr][cc]);
                }
        }
    }
}

// ---------------- inverse FFT: ONE row per block, N/2 real-IFFT trick ------
__global__ void fft_inv_kernel(float* __restrict__ out) {
    __shared__ float2 buf[2048];
    int r = blockIdx.x;   // 0..127
    const float2* P0 = d_OutfP[0] + (size_t)r * NBINS;
    const float2* P1 = d_OutfP[1] + (size_t)r * NBINS;
    for (int s = threadIdx.x; s < 2048; s += 256) {
        int ms = 2048 - s;
        float2 Yf = make_float2(P0[s].x + P1[s].x,  P0[s].y + P1[s].y);
        float2 Ym = make_float2(P0[ms].x + P1[ms].x, P0[ms].y + P1[ms].y);
        float2 A = make_float2(0.5f * (Yf.x + Ym.x), 0.5f * (Yf.y - Ym.y));
        float2 D = make_float2(0.5f * (Yf.x - Ym.x), 0.5f * (Yf.y + Ym.y));
        float2 tw = d_tw4[s];
        float2 B = make_float2(D.x * tw.x + D.y * tw.y,
                               D.y * tw.x - D.x * tw.y);
        float2 Z = make_float2(A.x - B.y, A.y + B.x);
        buf[addr2048(s)] = make_float2(Z.x, -Z.y);
    }
    fft2048_core(buf);
    const float inv = 1.0f / 2048.0f;
    float2* out2 = (float2*)out;
    for (int k = threadIdx.x; k < 1024; k += 256) {
        float2 F = buf[k];
        out2[r * 1024 + k] = make_float2(F.x * inv, -F.y * inv);
    }
}

// ============================================================================
extern "C" void kernel_launch(void* const* d_in, const int* in_sizes, int n_in,
                              void* d_out, int out_size) {
    (void)in_sizes; (void)n_in; (void)out_size;
    const float* x  = (const float*)d_in[0];
    const float* W1 = (const float*)d_in[1];
    const float* W2 = (const float*)d_in[2];
    const float* W3 = (const float*)d_in[3];
    float* out = (float*)d_out;

    cudaFuncSetAttribute(k45_kernel,
                         cudaFuncAttributeMaxDynamicSharedMemorySize, K45_SMEM);
    cudaFuncSetAttribute(setup_h2_kernel,
                         cudaFuncAttributeMaxDynamicSharedMemorySize, SETUP_SMEM);

    setup_h2_kernel<<<128, 256, SETUP_SMEM>>>(W1, W2, W3);
    fft_gx_kernel<<<128, 512>>>(x);
    k45_kernel<<<dim3(129, 2), 256, K45_SMEM>>>();
    fft_inv_kernel<<<128, 256>>>(out);
}

// round 16
// speedup vs baseline: 1.0551x; 1.0546x over previous
#include <cuda_runtime.h>
#include <math.h>

// ============================================================================
// CKConv via FFT convolution, fused tf32 tensor-core spectrum GEMM.
//   Outf[b,o,f] = Σ_i Xf[b,i,f] · Σ_m Gf[m,f]·W3[m,o*64+i]    (Kf never stored)
// k45: RI-PACKED MMA (M = 8 f's x {Re,Im}), full K=128 per block, grid 257,
// 3-buffer depth-2 cp.async ring. Radix-8 forward FFTs, N/2-trick inverse.
// ============================================================================

#define LL     2048
#define NFFT   4096
#define HID    128
#define NBINS  2049   // NFFT/2 + 1

__device__ float  d_h2T[HID * LL];          // [m][l]
__device__ float4 d_W3f4[64 * 8 * 8 * 32];  // [i][warp][kc2][lane] frag quads
__device__ float2 d_tw4[NFFT];
__device__ float2 d_Gf[HID * NFFT];         // [m][f] tf32-rounded, mirrored
__device__ float2 d_Xf[128 * NFFT];         // [b*64+i][f], mirrored
__device__ float2 d_Outf[128 * NBINS];      // [b*64+o][f]

__device__ __forceinline__ float to_tf32(float x) {
    unsigned u;
    asm("cvt.rna.tf32.f32 %0, %1;" : "=r"(u) : "f"(x));
    return __uint_as_float(u);
}

// -------------- fused: SIREN h2 + twiddles + W3 fragment repack ------------
// (exact R12 version — 69.7us configuration)
__global__ void setup_h2_kernel(const float* __restrict__ W1,
                                const float* __restrict__ W2,
                                const float* __restrict__ W3) {
    __shared__ float h1[HID];
    const int tid = threadIdx.x;
    const int l   = blockIdx.x;     // 0..2047

    if (tid < HID) {
        float rel = -1.0f + 2.0f * (float)l / 2047.0f;
        h1[tid] = sinf(30.0f * rel * W1[tid]);
    }
    __syncthreads();
    if (tid < HID) {
        float acc = 0.0f;
#pragma unroll 16
        for (int m = 0; m < HID; m++)
            acc += h1[m] * W2[m * HID + tid];
        d_h2T[tid * LL + l] = sinf(30.0f * acc);
    } else if (tid < HID + 64) {
        int idx = blockIdx.x * 64 + (tid - HID);   // 0..131071
        if (idx < NFFT) {
            double a = 2.0 * 3.14159265358979323846 * (double)idx / (double)NFFT;
            d_tw4[idx] = make_float2((float)cos(a), (float)(-sin(a)));
        }
        int lane = idx & 31;
        int kc2  = (idx >> 5) & 7;
        int w    = (idx >> 8) & 7;
        int i    = idx >> 11;
        int tg = lane & 3, g = lane >> 2;
        int col = (w * 8 + g) * 64 + i;
        int mA  = (2 * kc2) * 8 + tg;
        int mB  = (2 * kc2 + 1) * 8 + tg;
        d_W3f4[idx] = make_float4(to_tf32(W3[mA * 4096 + col]),
                                  to_tf32(W3[(mA + 4) * 4096 + col]),
                                  to_tf32(W3[mB * 4096 + col]),
                                  to_tf32(W3[(mB + 4) * 4096 + col]));
    }
}

// ------------------------------------------------------------- FFT helpers --
__device__ __forceinline__ int rev8(int d) {
    return ((d & 7) << 9) | (((d >> 3) & 7) << 6) |
           (((d >> 6) & 7) << 3) | ((d >> 9) & 7);
}
__device__ __forceinline__ float2 cmul(float2 a, float2 b) {
    return make_float2(a.x * b.x - a.y * b.y, a.x * b.y + a.y * b.x);
}
#define SQRT1_2 0.70710678118654752f

__device__ __forceinline__ void bfly8(float2* u) {
    float2 ea = make_float2(u[0].x + u[4].x, u[0].y + u[4].y);
    float2 eb = make_float2(u[0].x - u[4].x, u[0].y - u[4].y);
    float2 ec = make_float2(u[2].x + u[6].x, u[2].y + u[6].y);
    float2 ed = make_float2(u[2].x - u[6].x, u[2].y - u[6].y);
    float2 E0 = make_float2(ea.x + ec.x, ea.y + ec.y);
    float2 E1 = make_float2(eb.x + ed.y, eb.y - ed.x);
    float2 E2 = make_float2(ea.x - ec.x, ea.y - ec.y);
    float2 E3 = make_float2(eb.x - ed.y, eb.y + ed.x);
    float2 oa = make_float2(u[1].x + u[5].x, u[1].y + u[5].y);
    float2 ob = make_float2(u[1].x - u[5].x, u[1].y - u[5].y);
    float2 oc = make_float2(u[3].x + u[7].x, u[3].y + u[7].y);
    float2 od = make_float2(u[3].x - u[7].x, u[3].y - u[7].y);
    float2 O0 = make_float2(oa.x + oc.x, oa.y + oc.y);
    float2 O1 = make_float2(ob.x + od.y, ob.y - od.x);
    float2 O2 = make_float2(oa.x - oc.x, oa.y - oc.y);
    float2 O3 = make_float2(ob.x - od.y, ob.y + od.x);
    float2 T1 = make_float2(SQRT1_2 * (O1.x + O1.y), SQRT1_2 * (O1.y - O1.x));
    float2 T2 = make_float2(O2.y, -O2.x);
    float2 T3 = make_float2(SQRT1_2 * (O3.y - O3.x), -SQRT1_2 * (O3.x + O3.y));
    u[0] = make_float2(E0.x + O0.x, E0.y + O0.y);
    u[4] = make_float2(E0.x - O0.x, E0.y - O0.y);
    u[1] = make_float2(E1.x + T1.x, E1.y + T1.y);
    u[5] = make_float2(E1.x - T1.x, E1.y - T1.y);
    u[2] = make_float2(E2.x + T2.x, E2.y + T2.y);
    u[6] = make_float2(E2.x - T2.x, E2.y - T2.y);
    u[3] = make_float2(E3.x + T3.x, E3.y + T3.y);
    u[7] = make_float2(E3.x - T3.x, E3.y - T3.y);
}

// ------------------- 4096-pt radix-8 core (512 threads, 4 stages) ----------
__device__ __forceinline__ void fft8_core(float2* buf) {
    const int tid = threadIdx.x;
    __syncthreads();
    {
        float4* b4 = (float4*)(buf + tid * 8);
        float2 u[8];
#pragma unroll
        for (int h = 0; h < 4; h++) {
            float4 v = b4[h];
            u[2 * h]     = make_float2(v.x, v.y);
            u[2 * h + 1] = make_float2(v.z, v.w);
        }
        bfly8(u);
#pragma unroll
        for (int h = 0; h < 4; h++)
            b4[h] = make_float4(u[2 * h].x, u[2 * h].y,
                                u[2 * h + 1].x, u[2 * h + 1].y);
    }
#pragma unroll
    for (int st = 1; st < 4; st++) {
        const int q = 1 << (3 * st);
        const int tstep = NFFT >> (3 * st + 3);
        __syncthreads();
        const int j = tid & (q - 1);
        const int base = ((tid >> (3 * st)) << (3 * st + 3)) + j;
        float2 u[8];
        u[0] = buf[base];
#pragma unroll
        for (int t = 1; t < 8; t++)
            u[t] = cmul(buf[base + t * q], d_tw4[j * t * tstep]);
        bfly8(u);
#pragma unroll
        for (int t = 0; t < 8; t++)
            buf[base + t * q] = u[t];
    }
    __syncthreads();
}

// --------------- 2048-pt mixed-radix [4,8,8,8] core (256 threads) ----------
__device__ __forceinline__ int addr2048(int s) {
    return (s >> 9) + 4 * ((s >> 6) & 7) + 32 * ((s >> 3) & 7) + 256 * (s & 7);
}
__device__ __forceinline__ void fft2048_core(float2* buf) {
    const int tid = threadIdx.x;
    __syncthreads();
#pragma unroll
    for (int k = 0; k < 2; k++) {
        float4* b4 = (float4*)(buf + ((tid + (k << 8)) << 2));
        float4 lo = b4[0], hi = b4[1];
        float2 u0 = make_float2(lo.x, lo.y), u1 = make_float2(lo.z, lo.w);
        float2 u2 = make_float2(hi.x, hi.y), u3 = make_float2(hi.z, hi.w);
        float2 a = make_float2(u0.x + u2.x, u0.y + u2.y);
        float2 b = make_float2(u0.x - u2.x, u0.y - u2.y);
        float2 c = make_float2(u1.x + u3.x, u1.y + u3.y);
        float2 d = make_float2(u1.x - u3.x, u1.y - u3.y);
        b4[0] = make_float4(a.x + c.x, a.y + c.y, b.x + d.y, b.y - d.x);
        b4[1] = make_float4(a.x - c.x, a.y - c.y, b.x - d.y, b.y + d.x);
    }
#pragma unroll
    for (int st = 0; st < 3; st++) {
        const int q = 4 << (3 * st);
        const int tstep = 128 >> (3 * st);
        const int sh = 2 + 3 * st;
        __syncthreads();
        const int j = tid & (q - 1);
        const int base = ((tid >> sh) << (sh + 3)) + j;
        float2 u[8];
        u[0] = buf[base];
#pragma unroll
        for (int t = 1; t < 8; t++)
            u[t] = cmul(buf[base + t * q], d_tw4[j * t * tstep]);
        bfly8(u);
#pragma unroll
        for (int t = 0; t < 8; t++)
            buf[base + t * q] = u[t];
    }
    __syncthreads();
}

// ---------------------------- forward FFTs, two real rows packed per block --
__global__ void fft_gx_kernel(const float* __restrict__ x) {
    __shared__ float2 buf[NFFT];
    int blk = blockIdx.x;
    bool isg = blk < 64;
    int r0 = isg ? 2 * blk : 2 * (blk - 64);
    for (int s = threadIdx.x; s < NFFT; s += 512) {
        float va = 0.0f, vb = 0.0f;
        if (s < LL) {
            if (isg) {
                va = d_h2T[r0 * LL + (LL - 1 - s)];
                vb = d_h2T[(r0 + 1) * LL + (LL - 1 - s)];
            } else {
                va = x[r0 * LL + s];
                vb = x[(r0 + 1) * LL + s];
            }
        }
        buf[rev8(s)] = make_float2(va, vb);
    }
    fft8_core(buf);
    for (int f = threadIdx.x; f <= 2048; f += 512) {
        float2 Zf = buf[f];
        float2 Zc = buf[(NFFT - f) & (NFFT - 1)];
        float2 A = make_float2((Zf.x + Zc.x) * 0.5f, (Zf.y - Zc.y) * 0.5f);
        float2 B = make_float2((Zf.y + Zc.y) * 0.5f, (Zc.x - Zf.x) * 0.5f);
        if (isg) {
            A = make_float2(to_tf32(A.x), to_tf32(A.y));
            B = make_float2(to_tf32(B.x), to_tf32(B.y));
            d_Gf[r0 * NFFT + f]       = A;
            d_Gf[(r0 + 1) * NFFT + f] = B;
            if (f > 0 && f < 2048) {
                d_Gf[r0 * NFFT + NFFT - f]       = make_float2(A.x, -A.y);
                d_Gf[(r0 + 1) * NFFT + NFFT - f] = make_float2(B.x, -B.y);
            }
        } else {
            d_Xf[r0 * NFFT + f]       = A;
            d_Xf[(r0 + 1) * NFFT + f] = B;
            if (f > 0 && f < 2048) {
                d_Xf[r0 * NFFT + NFFT - f]       = make_float2(A.x, -A.y);
                d_Xf[(r0 + 1) * NFFT + NFFT - f] = make_float2(B.x, -B.y);
            }
        }
    }
}

// ---------------- k45: RI-packed MMA, full K, fused per-bin mixing ---------
// A tile (M=16): rows 0-7 = Re Gf[f0..f0+7], rows 8-15 = Im Gf[f0..f0+7].
// One MMA per k-step computes Re+Im of Kf[8f x 8o]. c[0..1]=Re, c[2..3]=Im.
#define MMA_TF32(C, A, B0, B1)                                              \
    asm volatile("mma.sync.aligned.m16n8k8.row.col.f32.tf32.tf32.f32 "      \
        "{%0,%1,%2,%3}, {%4,%5,%6,%7}, {%8,%9}, {%0,%1,%2,%3};"             \
        : "+f"(C[0]), "+f"(C[1]), "+f"(C[2]), "+f"(C[3])                    \
        : "r"(A[0]), "r"(A[1]), "r"(A[2]), "r"(A[3]), "r"(B0), "r"(B1))

#define CP16(dst_u32, src_ptr)                                              \
    asm volatile("cp.async.cg.shared.global [%0], [%1], 16;"                \
                 :: "r"(dst_u32), "l"(src_ptr))

#define XS_FLOATS   (128 * 8 * 2)               // 1024 float2 = 8 KB
#define SLICE_F4    256                         // float4 per buffer (4 KB)
#define K45_SMEM    (XS_FLOATS * 4 + 8 * 3 * SLICE_F4 * 16)   // 104 KB

__global__ void __launch_bounds__(256, 2) k45_kernel() {
    extern __shared__ float smem[];
    float2* Xs = (float2*)smem;                 // [i][ff(8)][b(2)]

    const int f0   = blockIdx.x * 8;            // grid 257: f0 <= 2048
    const int tid  = threadIdx.x;
    const int lane = tid & 31;
    const int warp = tid >> 5;
    const int g    = lane >> 2;
    const int tg   = lane & 3;
    const int obase = warp * 8;

    float4* Bw = (float4*)(smem + XS_FLOATS) + warp * (3 * SLICE_F4);
    unsigned bw_base = (unsigned)__cvta_generic_to_shared(Bw);

    // per-warp slice: full K (8 kc2 quads) = 256 float4 = 4 KB
#define LOAD_SLICE(i_, buf_)                                                \
    {                                                                       \
        const float4* srcb = d_W3f4 + ((i_) * 8 + warp) * 256;              \
        unsigned dstb = bw_base + (buf_) * (SLICE_F4 * 16);                 \
        _Pragma("unroll")                                                   \
        for (int j = 0; j < 8; j++)                                         \
            CP16(dstb + (lane + (j << 5)) * 16, srcb + lane + (j << 5));    \
    }

    LOAD_SLICE(0, 0); asm volatile("cp.async.commit_group;");
    LOAD_SLICE(1, 1); asm volatile("cp.async.commit_group;");

    // Xs fill: [i][ff][b] so both batches for one (i,f) are one float4
    for (int idx = tid; idx < 128 * 8; idx += 256) {
        int row = idx >> 3, ff = idx & 7;
        int b = row >> 6, i = row & 63;
        Xs[(i * 8 + ff) * 2 + b] = d_Xf[row * NFFT + f0 + ff];
    }

    // A fragments: 16 k-steps, RI-packed (a = {Re@tg, Im@tg, Re@tg+4, Im@tg+4})
    unsigned a[16][4];
#pragma unroll
    for (int k0 = 0; k0 < 16; k0++) {
        float2 v0 = d_Gf[(k0 * 8 + tg)     * NFFT + f0 + g];
        float2 v1 = d_Gf[(k0 * 8 + tg + 4) * NFFT + f0 + g];
        a[k0][0] = __float_as_uint(v0.x);
        a[k0][1] = __float_as_uint(v0.y);
        a[k0][2] = __float_as_uint(v1.x);
        a[k0][3] = __float_as_uint(v1.y);
    }

    float oR[2][2] = {}, oI[2][2] = {};          // [b][cc]
    float c0[4], c1[4];                          // even/odd k-step chains

#define EPILOGUE(ip_)                                                       \
    {                                                                       \
        float4 xv4 = ((const float4*)Xs)[(ip_) * 8 + g];                    \
        float kr0 = c0[0] + c1[0], kr1 = c0[1] + c1[1];                     \
        float ki0 = c0[2] + c1[2], ki1 = c0[3] + c1[3];                     \
        oR[0][0] += xv4.x * kr0 - xv4.y * ki0;                              \
        oI[0][0] += xv4.x * ki0 + xv4.y * kr0;                              \
        oR[0][1] += xv4.x * kr1 - xv4.y * ki1;                              \
        oI[0][1] += xv4.x * ki1 + xv4.y * kr1;                              \
        oR[1][0] += xv4.z * kr0 - xv4.w * ki0;                              \
        oI[1][0] += xv4.z * ki0 + xv4.w * kr0;                              \
        oR[1][1] += xv4.z * kr1 - xv4.w * ki1;                              \
        oI[1][1] += xv4.z * ki1 + xv4.w * kr1;                              \
    }

    __syncthreads();     // Xs visible; last block-wide barrier.

#pragma unroll 3
    for (int i = 0; i < 64; i++) {
        if (i + 2 < 64) LOAD_SLICE(i + 2, (i + 2) % 3);
        asm volatile("cp.async.commit_group;");      // real or empty group
        asm volatile("cp.async.wait_group 2;");      // slice i is ready
        __syncwarp();

        if (i > 0) EPILOGUE(i - 1);                  // deferred: MMA latency hidden

#pragma unroll
        for (int j = 0; j < 4; j++) { c0[j] = 0.f; c1[j] = 0.f; }
        const float4* Bp = Bw + (i % 3) * SLICE_F4 + lane;
#pragma unroll
        for (int q = 0; q < 8; q++) {
            float4 bv = Bp[q * 32];
            unsigned b0 = __float_as_uint(bv.x), b1 = __float_as_uint(bv.y);
            unsigned b2 = __float_as_uint(bv.z), b3 = __float_as_uint(bv.w);
            MMA_TF32(c0, a[2 * q],     b0, b1);
            MMA_TF32(c1, a[2 * q + 1], b2, b3);
        }
    }
    EPILOGUE(63);

    int f = f0 + g;
    if (f < NBINS) {
#pragma unroll
        for (int b = 0; b < 2; b++)
#pragma unroll
            for (int cc = 0; cc < 2; cc++) {
                int o = obase + tg * 2 + cc;
                d_Outf[(b * 64 + o) * NBINS + f] =
                    make_float2(oR[b][cc], oI[b][cc]);
            }
    }
}

// ---------------- inverse FFT: ONE row per block, N/2 real-IFFT trick ------
__global__ void fft_inv_kernel(float* __restrict__ out) {
    __shared__ float2 buf[2048];
    int r = blockIdx.x;   // 0..127
    const float2* P0 = d_Outf + (size_t)r * NBINS;
    for (int s = threadIdx.x; s < 2048; s += 256) {
        int ms = 2048 - s;
        float2 Yf = P0[s];
        float2 Ym = P0[ms];
        float2 A = make_float2(0.5f * (Yf.x + Ym.x), 0.5f * (Yf.y - Ym.y));
        float2 D = make_float2(0.5f * (Yf.x - Ym.x), 0.5f * (Yf.y + Ym.y));
        float2 tw = d_tw4[s];
        float2 B = make_float2(D.x * tw.x + D.y * tw.y,
                               D.y * tw.x - D.x * tw.y);
        float2 Z = make_float2(A.x - B.y, A.y + B.x);
        buf[addr2048(s)] = make_float2(Z.x, -Z.y);
    }
    fft2048_core(buf);
    const float inv = 1.0f / 2048.0f;
    float2* out2 = (float2*)out;
    for (int k = threadIdx.x; k < 1024; k += 256) {
        float2 F = buf[k];
        out2[r * 1024 + k] = make_float2(F.x * inv, -F.y * inv);
    }
}

// ============================================================================
extern "C" void kernel_launch(void* const* d_in, const int* in_sizes, int n_in,
                              void* d_out, int out_size) {
    (void)in_sizes; (void)n_in; (void)out_size;
    const float* x  = (const float*)d_in[0];
    const float* W1 = (const float*)d_in[1];
    const float* W2 = (const float*)d_in[2];
    const float* W3 = (const float*)d_in[3];
    float* out = (float*)d_out;

    cudaFuncSetAttribute(k45_kernel,
                         cudaFuncAttributeMaxDynamicSharedMemorySize, K45_SMEM);

    setup_h2_kernel<<<2048, 256>>>(W1, W2, W3);
    fft_gx_kernel<<<128, 512>>>(x);
    k45_kernel<<<257, 256, K45_SMEM>>>();
    fft_inv_kernel<<<128, 256>>>(out);
}